// round 2
// baseline (speedup 1.0000x reference)
#include <cuda_runtime.h>
#include <cuda_bf16.h>
#include <cstdint>
#include <cstddef>

// Problem constants
#define BB   4
#define TT   2048
#define DM   1024
#define DI   2048   // d_inner
#define DX   4096   // 2*d_inner (xz row width)
#define MROWS (BB*TT)   // 8192

// ---------------- scratch (__device__ globals; no allocation allowed) -------
__device__ float g_xz [(size_t)MROWS * DX];   // [8192,4096]  xi | z
__device__ float g_lam[(size_t)MROWS * DI];   // [8192,2048]
__device__ float g_v  [(size_t)MROWS * DI];   // [8192,2048]
__device__ float g_g  [(size_t)MROWS * DI];   // silu(z)*h
__device__ float g_ivv[(size_t)MROWS];        // 1/(v.v) per (b,t)

// ---------------- generic NT GEMM: C[M,N] = A[M,K] * B[N,K]^T (+bias, epi) --
// mode 0: C = acc + bias (bias may be null)
// mode 1: C = exp(-8*softplus(omega[col]) * sigmoid(acc + bias[col]))
__global__ __launch_bounds__(256) void gemm_nt(
    const float* __restrict__ A, int lda,
    const float* __restrict__ B, int ldb,
    float* __restrict__ C, int ldc,
    int K,
    const float* __restrict__ bias,
    const float* __restrict__ omega,
    int mode)
{
    __shared__ float As[2][8][128];
    __shared__ float Bs[2][8][128];

    const int tid = threadIdx.x;
    const int tx = tid & 15;       // 0..15 -> col groups of 8
    const int ty = tid >> 4;       // 0..15 -> row groups of 8
    const int rowBase = blockIdx.y * 128;
    const int colBase = blockIdx.x * 128;

    const int lrow = tid >> 1;           // 0..127
    const int lcol = (tid & 1) << 2;     // 0 or 4

    const float* Aptr = A + (size_t)(rowBase + lrow) * lda + lcol;
    const float* Bptr = B + (size_t)(colBase + lrow) * ldb + lcol;

    // prologue: tile 0 -> buffer 0
    {
        float4 a4 = *(const float4*)Aptr;
        float4 b4 = *(const float4*)Bptr;
        As[0][lcol+0][lrow] = a4.x; As[0][lcol+1][lrow] = a4.y;
        As[0][lcol+2][lrow] = a4.z; As[0][lcol+3][lrow] = a4.w;
        Bs[0][lcol+0][lrow] = b4.x; Bs[0][lcol+1][lrow] = b4.y;
        Bs[0][lcol+2][lrow] = b4.z; Bs[0][lcol+3][lrow] = b4.w;
    }
    __syncthreads();

    float acc[8][8];
    #pragma unroll
    for (int i = 0; i < 8; i++)
        #pragma unroll
        for (int j = 0; j < 8; j++) acc[i][j] = 0.f;

    const int nt = K >> 3;
    int buf = 0;

    for (int kt = 0; kt < nt; kt++) {
        float4 a4n, b4n;
        const bool more = (kt + 1 < nt);
        if (more) {
            a4n = *(const float4*)(Aptr + (size_t)(kt + 1) * 8);
            b4n = *(const float4*)(Bptr + (size_t)(kt + 1) * 8);
        }
        #pragma unroll
        for (int k = 0; k < 8; k++) {
            float ar[8], br[8];
            *(float4*)&ar[0] = *(const float4*)&As[buf][k][ty * 8];
            *(float4*)&ar[4] = *(const float4*)&As[buf][k][ty * 8 + 4];
            *(float4*)&br[0] = *(const float4*)&Bs[buf][k][tx * 8];
            *(float4*)&br[4] = *(const float4*)&Bs[buf][k][tx * 8 + 4];
            #pragma unroll
            for (int i = 0; i < 8; i++)
                #pragma unroll
                for (int j = 0; j < 8; j++)
                    acc[i][j] += ar[i] * br[j];
        }
        if (more) {
            buf ^= 1;
            As[buf][lcol+0][lrow] = a4n.x; As[buf][lcol+1][lrow] = a4n.y;
            As[buf][lcol+2][lrow] = a4n.z; As[buf][lcol+3][lrow] = a4n.w;
            Bs[buf][lcol+0][lrow] = b4n.x; Bs[buf][lcol+1][lrow] = b4n.y;
            Bs[buf][lcol+2][lrow] = b4n.z; Bs[buf][lcol+3][lrow] = b4n.w;
            __syncthreads();
        }
    }

    // epilogue
    float bcol[8], fcol[8];
    #pragma unroll
    for (int j = 0; j < 8; j++) {
        const int c = colBase + tx * 8 + j;
        bcol[j] = bias ? bias[c] : 0.f;
        fcol[j] = (mode == 1) ? (-8.0f * log1pf(expf(omega[c]))) : 0.f;
    }

    #pragma unroll
    for (int i = 0; i < 8; i++) {
        const int r = rowBase + ty * 8 + i;
        float out[8];
        #pragma unroll
        for (int j = 0; j < 8; j++) {
            float val = acc[i][j] + bcol[j];
            if (mode == 1) {
                const float sig = 1.0f / (1.0f + expf(-val));
                val = expf(fcol[j] * sig);
            }
            out[j] = val;
        }
        float* Crow = C + (size_t)r * ldc + colBase + tx * 8;
        *(float4*)(Crow + 0) = *(float4*)&out[0];
        *(float4*)(Crow + 4) = *(float4*)&out[4];
    }
}

// ---------------- 1/(v.v) per row ------------------------------------------
__global__ __launch_bounds__(256) void vv_kernel(const float* __restrict__ v,
                                                 float* __restrict__ ivv)
{
    __shared__ float sm[8];
    const int row = blockIdx.x, tid = threadIdx.x;
    const float4* vr = (const float4*)(v + (size_t)row * DI);
    float s = 0.f;
    #pragma unroll
    for (int i = 0; i < 2; i++) {
        float4 a = vr[tid + i * 256];
        s += a.x * a.x + a.y * a.y + a.z * a.z + a.w * a.w;
    }
    #pragma unroll
    for (int o = 16; o; o >>= 1) s += __shfl_xor_sync(0xffffffffu, s, o);
    if ((tid & 31) == 0) sm[tid >> 5] = s;
    __syncthreads();
    if (tid == 0) {
        float t = 0.f;
        #pragma unroll
        for (int w = 0; w < 8; w++) t += sm[w];
        ivv[row] = 1.0f / t;
    }
}

// ---------------- sequential scan: one CTA per batch ------------------------
// h_t = lam_t*(h_{t-1} - 2*(v.h/v.v)*v_t) + (1-lam_t)*xi_t ; g_t = silu(z_t)*h_t
__global__ __launch_bounds__(1024) void scan_kernel(
    const float* __restrict__ xz,   // [8192,4096] xi|z
    const float* __restrict__ lam,  // [8192,2048]
    const float* __restrict__ v,    // [8192,2048]
    const float* __restrict__ ivv,  // [8192]
    float* __restrict__ g)          // [8192,2048]
{
    __shared__ float red[33];
    const int b = blockIdx.x;
    const int tid = threadIdx.x;
    const int n2 = tid * 2;

    const float* xib  = xz  + (size_t)b * TT * DX;
    const float* zb   = xib + DI;
    const float* lamb = lam + (size_t)b * TT * DI;
    const float* vb   = v   + (size_t)b * TT * DI;
    const float* ivvb = ivv + (size_t)b * TT;
    float*       gb   = g   + (size_t)b * TT * DI;

    float2 h = *(const float2*)(xib + n2);
    {   // t = 0 output
        float2 z0 = *(const float2*)(zb + n2);
        float2 g0;
        g0.x = z0.x / (1.0f + expf(-z0.x)) * h.x;
        g0.y = z0.y / (1.0f + expf(-z0.y)) * h.y;
        *(float2*)(gb + n2) = g0;
    }

    for (int t = 1; t < TT; t++) {
        const size_t o2 = (size_t)t * DI + n2;
        const size_t o4 = (size_t)t * DX + n2;
        const float2 vt = *(const float2*)(vb + o2);
        float p = vt.x * h.x + vt.y * h.y;

        // prefetch step-t operands (independent of the reduction)
        const float2 lt = *(const float2*)(lamb + o2);
        const float2 xt = *(const float2*)(xib + o4);
        const float2 zt = *(const float2*)(zb  + o4);

        #pragma unroll
        for (int o = 16; o; o >>= 1) p += __shfl_xor_sync(0xffffffffu, p, o);
        if ((tid & 31) == 0) red[tid >> 5] = p;
        __syncthreads();
        if (tid < 32) {
            float q = red[tid];
            #pragma unroll
            for (int o = 16; o; o >>= 1) q += __shfl_xor_sync(0xffffffffu, q, o);
            if (tid == 0) red[32] = q;
        }
        __syncthreads();

        const float s2 = 2.0f * red[32] * ivvb[t];
        h.x = lt.x * (h.x - s2 * vt.x) + (1.0f - lt.x) * xt.x;
        h.y = lt.y * (h.y - s2 * vt.y) + (1.0f - lt.y) * xt.y;

        float2 gt;
        gt.x = zt.x / (1.0f + expf(-zt.x)) * h.x;
        gt.y = zt.y / (1.0f + expf(-zt.y)) * h.y;
        *(float2*)(gb + o2) = gt;
    }
}

// ---------------- launcher ---------------------------------------------------
extern "C" void kernel_launch(void* const* d_in, const int* in_sizes, int n_in,
                              void* d_out, int out_size)
{
    const float* x     = (const float*)d_in[0];   // [4,2048,1024]
    const float* omega = (const float*)d_in[1];   // [2048]
    const float* Win   = (const float*)d_in[2];   // [4096,1024]
    const float* Wl    = (const float*)d_in[3];   // [2048,2048]
    const float* bl    = (const float*)d_in[4];   // [2048]
    const float* Wv    = (const float*)d_in[5];   // [2048,2048]
    const float* bv    = (const float*)d_in[6];   // [2048]
    const float* Wout  = (const float*)d_in[7];   // [1024,2048]
    float* out = (float*)d_out;                   // [4,2048,1024]

    float* xz;  cudaGetSymbolAddress((void**)&xz,  g_xz);
    float* lam; cudaGetSymbolAddress((void**)&lam, g_lam);
    float* v;   cudaGetSymbolAddress((void**)&v,   g_v);
    float* gg;  cudaGetSymbolAddress((void**)&gg,  g_g);
    float* ivv; cudaGetSymbolAddress((void**)&ivv, g_ivv);

    // 1) xz = x @ Win^T           [8192,4096]
    gemm_nt<<<dim3(DX / 128, MROWS / 128), 256>>>(
        x, DM, Win, DM, xz, DX, DM, nullptr, nullptr, 0);

    // 2) lam = exp(-8*softplus(omega)*sigmoid(xi @ Wl^T + bl))
    gemm_nt<<<dim3(DI / 128, MROWS / 128), 256>>>(
        xz, DX, Wl, DI, lam, DI, DI, bl, omega, 1);

    // 3) v = xi @ Wv^T + bv
    gemm_nt<<<dim3(DI / 128, MROWS / 128), 256>>>(
        xz, DX, Wv, DI, v, DI, DI, bv, nullptr, 0);

    // 4) ivv = 1/(v.v) per row
    vv_kernel<<<MROWS, 256>>>(v, ivv);

    // 5) sequential scan -> g = silu(z) * h
    scan_kernel<<<BB, 1024>>>(xz, lam, v, ivv, gg);

    // 6) out = g @ Wout^T
    gemm_nt<<<dim3(DM / 128, MROWS / 128), 256>>>(
        gg, DI, Wout, DI, out, DM, DI, nullptr, nullptr, 0);
}

// round 4
// speedup vs baseline: 1.9178x; 1.9178x over previous
#include <cuda_runtime.h>
#include <cuda_bf16.h>
#include <cstdint>
#include <cstddef>

// Problem constants
#define BB   4
#define TT   2048
#define DM   1024
#define DI   2048
#define DX   4096
#define MROWS (BB*TT)   // 8192

// GEMM tiling
#define BKC   32                 // fp32/bf16 k elems per chunk
#define PITCH 40                 // bf16 elems per smem row (32 + 8 pad)
#define TILE_ELEMS (128*PITCH)   // 5120 bf16
#define TILE_BYTES (TILE_ELEMS*2)
#define GEMM_SMEM (8*TILE_BYTES + 1024)   // 4 A tiles + 4 B tiles + bias/fcol

// ---------------- scratch ----------------------------------------------------
__device__ float g_xz [(size_t)MROWS * DX];
__device__ float g_lam[(size_t)MROWS * DI];
__device__ float g_v  [(size_t)MROWS * DI];
__device__ float g_g  [(size_t)MROWS * DI];
__device__ float g_ivv[(size_t)MROWS];

// ---------------- mma.sync helper ---------------------------------------------
__device__ __forceinline__ void mma_bf16(float* c, const uint32_t* a, const uint32_t* b) {
    asm volatile(
        "mma.sync.aligned.m16n8k16.row.col.f32.bf16.bf16.f32 "
        "{%0,%1,%2,%3}, {%4,%5,%6,%7}, {%8,%9}, {%0,%1,%2,%3};"
        : "+f"(c[0]), "+f"(c[1]), "+f"(c[2]), "+f"(c[3])
        : "r"(a[0]), "r"(a[1]), "r"(a[2]), "r"(a[3]), "r"(b[0]), "r"(b[1]));
}

// fp32x4 -> hi/lo bf16 split, stored as uint2 (4 bf16) each
__device__ __forceinline__ void store_split(__nv_bfloat16* hi, __nv_bfloat16* lo,
                                            int off, float4 f) {
    __nv_bfloat162 h0 = __float22bfloat162_rn(make_float2(f.x, f.y));
    __nv_bfloat162 h1 = __float22bfloat162_rn(make_float2(f.z, f.w));
    float2 g0 = __bfloat1622float2(h0);
    float2 g1 = __bfloat1622float2(h1);
    __nv_bfloat162 l0 = __float22bfloat162_rn(make_float2(f.x - g0.x, f.y - g0.y));
    __nv_bfloat162 l1 = __float22bfloat162_rn(make_float2(f.z - g1.x, f.w - g1.y));
    uint2 hv, lv;
    hv.x = *(uint32_t*)&h0; hv.y = *(uint32_t*)&h1;
    lv.x = *(uint32_t*)&l0; lv.y = *(uint32_t*)&l1;
    *(uint2*)(hi + off) = hv;
    *(uint2*)(lo + off) = lv;
}

// ---------------- NT GEMM: C[M,N] = A[M,K] * B[N,K]^T (+bias, epilogue) -------
// mode 0: C = acc + bias ; mode 1: C = exp(-8*softplus(omega)*sigmoid(acc+bias))
__global__ __launch_bounds__(256, 1) void gemm_tc(
    const float* __restrict__ A, int lda,
    const float* __restrict__ B, int ldb,
    float* __restrict__ C, int ldc, int K,
    const float* __restrict__ bias,
    const float* __restrict__ omega, int mode)
{
    extern __shared__ char smraw[];
    __nv_bfloat16* sA = (__nv_bfloat16*)smraw;                      // 4 tiles: [stage][hi/lo]
    __nv_bfloat16* sB = (__nv_bfloat16*)(smraw + 4 * TILE_BYTES);   // 4 tiles
    float* bias_s = (float*)(smraw + 8 * TILE_BYTES);
    float* fcol_s = bias_s + 128;

    const int tid = threadIdx.x;
    const int wid = tid >> 5, lane = tid & 31;
    const int g = lane >> 2, tq = lane & 3;
    const int wm = wid >> 2, wn = wid & 3;       // warp grid 2 x 4, tiles 64 x 32
    const int rowBase = blockIdx.y * 128;
    const int colBase = blockIdx.x * 128;

    if (tid < 128) {
        int c = colBase + tid;
        bias_s[tid] = bias ? bias[c] : 0.f;
        fcol_s[tid] = (mode == 1) ? (-8.0f * log1pf(__expf(omega[c]))) : 0.f;
    }

    const int nc = K / BKC;
    float4 ra[4], rb[4];

    // prologue: load chunk 0
    #pragma unroll
    for (int i = 0; i < 4; i++) {
        const int idx = i * 256 + tid, row = idx >> 3, kq = idx & 7;
        ra[i] = *(const float4*)(A + (size_t)(rowBase + row) * lda + kq * 4);
        rb[i] = *(const float4*)(B + (size_t)(colBase + row) * ldb + kq * 4);
    }
    #pragma unroll
    for (int i = 0; i < 4; i++) {
        const int idx = i * 256 + tid, row = idx >> 3, kq = idx & 7;
        const int off = row * PITCH + kq * 4;
        store_split(sA, sA + TILE_ELEMS, off, ra[i]);
        store_split(sB, sB + TILE_ELEMS, off, rb[i]);
    }
    __syncthreads();

    float acc[4][4][4];
    #pragma unroll
    for (int mt = 0; mt < 4; mt++)
        #pragma unroll
        for (int nt = 0; nt < 4; nt++)
            #pragma unroll
            for (int j = 0; j < 4; j++) acc[mt][nt][j] = 0.f;

    for (int c = 0; c < nc; c++) {
        const int s = c & 1;
        if (c + 1 < nc) {
            const int kb = (c + 1) * BKC;
            #pragma unroll
            for (int i = 0; i < 4; i++) {
                const int idx = i * 256 + tid, row = idx >> 3, kq = idx & 7;
                ra[i] = *(const float4*)(A + (size_t)(rowBase + row) * lda + kb + kq * 4);
                rb[i] = *(const float4*)(B + (size_t)(colBase + row) * ldb + kb + kq * 4);
            }
        }

        const __nv_bfloat16* Ah = sA + (s * 2 + 0) * TILE_ELEMS;
        const __nv_bfloat16* Al = sA + (s * 2 + 1) * TILE_ELEMS;
        const __nv_bfloat16* Bh = sB + (s * 2 + 0) * TILE_ELEMS;
        const __nv_bfloat16* Bl = sB + (s * 2 + 1) * TILE_ELEMS;

        #pragma unroll
        for (int kk = 0; kk < 2; kk++) {
            const int kc = kk * 16 + tq * 2;
            uint32_t ah[4][4], al[4][4], bh[4][2], bl[4][2];
            #pragma unroll
            for (int mt = 0; mt < 4; mt++) {
                const int r0 = wm * 64 + mt * 16 + g;
                ah[mt][0] = *(const uint32_t*)(Ah + r0 * PITCH + kc);
                ah[mt][1] = *(const uint32_t*)(Ah + (r0 + 8) * PITCH + kc);
                ah[mt][2] = *(const uint32_t*)(Ah + r0 * PITCH + kc + 8);
                ah[mt][3] = *(const uint32_t*)(Ah + (r0 + 8) * PITCH + kc + 8);
                al[mt][0] = *(const uint32_t*)(Al + r0 * PITCH + kc);
                al[mt][1] = *(const uint32_t*)(Al + (r0 + 8) * PITCH + kc);
                al[mt][2] = *(const uint32_t*)(Al + r0 * PITCH + kc + 8);
                al[mt][3] = *(const uint32_t*)(Al + (r0 + 8) * PITCH + kc + 8);
            }
            #pragma unroll
            for (int nt = 0; nt < 4; nt++) {
                const int r = wn * 32 + nt * 8 + g;
                bh[nt][0] = *(const uint32_t*)(Bh + r * PITCH + kc);
                bh[nt][1] = *(const uint32_t*)(Bh + r * PITCH + kc + 8);
                bl[nt][0] = *(const uint32_t*)(Bl + r * PITCH + kc);
                bl[nt][1] = *(const uint32_t*)(Bl + r * PITCH + kc + 8);
            }
            #pragma unroll
            for (int mt = 0; mt < 4; mt++)
                #pragma unroll
                for (int nt = 0; nt < 4; nt++)
                    mma_bf16(acc[mt][nt], ah[mt], bh[nt]);
            #pragma unroll
            for (int mt = 0; mt < 4; mt++)
                #pragma unroll
                for (int nt = 0; nt < 4; nt++)
                    mma_bf16(acc[mt][nt], ah[mt], bl[nt]);
            #pragma unroll
            for (int mt = 0; mt < 4; mt++)
                #pragma unroll
                for (int nt = 0; nt < 4; nt++)
                    mma_bf16(acc[mt][nt], al[mt], bh[nt]);
        }

        if (c + 1 < nc) {
            const int s1 = s ^ 1;
            __nv_bfloat16* dAh = sA + (s1 * 2 + 0) * TILE_ELEMS;
            __nv_bfloat16* dAl = sA + (s1 * 2 + 1) * TILE_ELEMS;
            __nv_bfloat16* dBh = sB + (s1 * 2 + 0) * TILE_ELEMS;
            __nv_bfloat16* dBl = sB + (s1 * 2 + 1) * TILE_ELEMS;
            #pragma unroll
            for (int i = 0; i < 4; i++) {
                const int idx = i * 256 + tid, row = idx >> 3, kq = idx & 7;
                const int off = row * PITCH + kq * 4;
                store_split(dAh, dAl, off, ra[i]);
                store_split(dBh, dBl, off, rb[i]);
            }
        }
        __syncthreads();
    }

    // epilogue
    #pragma unroll
    for (int mt = 0; mt < 4; mt++) {
        const int r0 = rowBase + wm * 64 + mt * 16 + g;
        #pragma unroll
        for (int nt = 0; nt < 4; nt++) {
            const int col = wn * 32 + nt * 8 + tq * 2;
            float v0 = acc[mt][nt][0] + bias_s[col];
            float v1 = acc[mt][nt][1] + bias_s[col + 1];
            float v2 = acc[mt][nt][2] + bias_s[col];
            float v3 = acc[mt][nt][3] + bias_s[col + 1];
            if (mode == 1) {
                const float f0 = fcol_s[col], f1 = fcol_s[col + 1];
                v0 = __expf(f0 * __frcp_rn(1.0f + __expf(-v0)));
                v1 = __expf(f1 * __frcp_rn(1.0f + __expf(-v1)));
                v2 = __expf(f0 * __frcp_rn(1.0f + __expf(-v2)));
                v3 = __expf(f1 * __frcp_rn(1.0f + __expf(-v3)));
            }
            float* p0 = C + (size_t)r0 * ldc + colBase + col;
            float* p1 = C + (size_t)(r0 + 8) * ldc + colBase + col;
            *(float2*)p0 = make_float2(v0, v1);
            *(float2*)p1 = make_float2(v2, v3);
        }
    }
}

// ---------------- 1/(v.v) per row --------------------------------------------
__global__ __launch_bounds__(256) void vv_kernel(const float* __restrict__ v,
                                                 float* __restrict__ ivv)
{
    __shared__ float sm[8];
    const int row = blockIdx.x, tid = threadIdx.x;
    const float4* vr = (const float4*)(v + (size_t)row * DI);
    float s = 0.f;
    #pragma unroll
    for (int i = 0; i < 2; i++) {
        float4 a = vr[tid + i * 256];
        s += a.x * a.x + a.y * a.y + a.z * a.z + a.w * a.w;
    }
    #pragma unroll
    for (int o = 16; o; o >>= 1) s += __shfl_xor_sync(0xffffffffu, s, o);
    if ((tid & 31) == 0) sm[tid >> 5] = s;
    __syncthreads();
    if (tid == 0) {
        float t = 0.f;
        #pragma unroll
        for (int w = 0; w < 8; w++) t += sm[w];
        ivv[row] = 1.0f / t;
    }
}

// ---------------- sequential scan: one CTA per batch --------------------------
// single __syncthreads per step; parity-double-buffered partials; all-warp final reduce
__global__ __launch_bounds__(1024) void scan_kernel(
    const float* __restrict__ xz, const float* __restrict__ lam,
    const float* __restrict__ v, const float* __restrict__ ivv,
    float* __restrict__ g)
{
    __shared__ float red[64];
    const int b = blockIdx.x;
    const int tid = threadIdx.x;
    const int lane = tid & 31, wrp = tid >> 5;
    const int n2 = tid * 2;

    const float* xib  = xz  + (size_t)b * TT * DX;
    const float* zb   = xib + DI;
    const float* lamb = lam + (size_t)b * TT * DI;
    const float* vb   = v   + (size_t)b * TT * DI;
    const float* ivvb = ivv + (size_t)b * TT;
    float*       gb   = g   + (size_t)b * TT * DI;

    float2 h = *(const float2*)(xib + n2);
    {
        float2 z0 = *(const float2*)(zb + n2);
        float2 g0;
        g0.x = z0.x * __frcp_rn(1.0f + __expf(-z0.x)) * h.x;
        g0.y = z0.y * __frcp_rn(1.0f + __expf(-z0.y)) * h.y;
        *(float2*)(gb + n2) = g0;
    }

    for (int t = 1; t < TT; t++) {
        const size_t o2 = (size_t)t * DI + n2;
        const size_t o4 = (size_t)t * DX + n2;
        const float2 vt = *(const float2*)(vb + o2);
        float p = vt.x * h.x + vt.y * h.y;

        // prefetch step-t operands (independent of reduction)
        const float2 lt = *(const float2*)(lamb + o2);
        const float2 xt = *(const float2*)(xib + o4);
        const float2 zt = *(const float2*)(zb  + o4);
        const float iv  = ivvb[t];

        #pragma unroll
        for (int o = 16; o; o >>= 1) p += __shfl_xor_sync(0xffffffffu, p, o);
        const int rbase = (t & 1) << 5;
        if (lane == 0) red[rbase + wrp] = p;
        __syncthreads();
        float q = red[rbase + lane];
        #pragma unroll
        for (int o = 16; o; o >>= 1) q += __shfl_xor_sync(0xffffffffu, q, o);

        const float s2 = 2.0f * q * iv;
        h.x = lt.x * (h.x - s2 * vt.x) + (1.0f - lt.x) * xt.x;
        h.y = lt.y * (h.y - s2 * vt.y) + (1.0f - lt.y) * xt.y;

        float2 gt;
        gt.x = zt.x * __frcp_rn(1.0f + __expf(-zt.x)) * h.x;
        gt.y = zt.y * __frcp_rn(1.0f + __expf(-zt.y)) * h.y;
        *(float2*)(gb + o2) = gt;
    }
}

// ---------------- launcher -----------------------------------------------------
extern "C" void kernel_launch(void* const* d_in, const int* in_sizes, int n_in,
                              void* d_out, int out_size)
{
    const float* x     = (const float*)d_in[0];
    const float* omega = (const float*)d_in[1];
    const float* Win   = (const float*)d_in[2];
    const float* Wl    = (const float*)d_in[3];
    const float* bl    = (const float*)d_in[4];
    const float* Wv    = (const float*)d_in[5];
    const float* bv    = (const float*)d_in[6];
    const float* Wout  = (const float*)d_in[7];
    float* out = (float*)d_out;

    float* xz;  cudaGetSymbolAddress((void**)&xz,  g_xz);
    float* lam; cudaGetSymbolAddress((void**)&lam, g_lam);
    float* v;   cudaGetSymbolAddress((void**)&v,   g_v);
    float* gg;  cudaGetSymbolAddress((void**)&gg,  g_g);
    float* ivv; cudaGetSymbolAddress((void**)&ivv, g_ivv);

    static int smem_set = 0;
    if (!smem_set) {
        cudaFuncSetAttribute(gemm_tc, cudaFuncAttributeMaxDynamicSharedMemorySize, GEMM_SMEM);
        smem_set = 1;
    }

    // 1) xz = x @ Win^T
    gemm_tc<<<dim3(DX / 128, MROWS / 128), 256, GEMM_SMEM>>>(
        x, DM, Win, DM, xz, DX, DM, nullptr, nullptr, 0);

    // 2) lam = exp(-8*softplus(omega)*sigmoid(xi @ Wl^T + bl))
    gemm_tc<<<dim3(DI / 128, MROWS / 128), 256, GEMM_SMEM>>>(
        xz, DX, Wl, DI, lam, DI, DI, bl, omega, 1);

    // 3) v = xi @ Wv^T + bv
    gemm_tc<<<dim3(DI / 128, MROWS / 128), 256, GEMM_SMEM>>>(
        xz, DX, Wv, DI, v, DI, DI, bv, nullptr, 0);

    // 4) 1/(v.v)
    vv_kernel<<<MROWS, 256>>>(v, ivv);

    // 5) scan
    scan_kernel<<<BB, 1024>>>(xz, lam, v, ivv, gg);

    // 6) out = g @ Wout^T
    gemm_tc<<<dim3(DM / 128, MROWS / 128), 256, GEMM_SMEM>>>(
        gg, DI, Wout, DI, out, DM, DI, nullptr, nullptr, 0);
}